// round 8
// baseline (speedup 1.0000x reference)
#include <cuda_runtime.h>
#include <math.h>
#include <cstdint>

#define Bn 4
#define Cc 256
#define Onc 256
#define Hh 64
#define Ww 64
#define Kk 9
#define HW 4096

typedef unsigned long long u64;

// Scratch (static device arrays — no allocation)
__device__ float g_buf1[Bn * Cc * HW];
__device__ float g_buf2[Bn * Cc * HW];
__device__ float g_wT[3 * Cc * Kk * Onc];       // main weights [l][c][k][o]
__device__ float g_woT[3 * Cc * Kk * 28];       // offset weights [l][c][tap][28]

// ---- packed f32x2 helpers -------------------------------------------------
#define FMA2(d, a, b)  asm("fma.rn.f32x2 %0, %1, %2, %0;" : "+l"(d) : "l"(a), "l"(b))
#define ADDP2(d, a)    asm("add.rn.f32x2 %0, %1, %0;" : "+l"(d) : "l"(a))

__device__ __forceinline__ u64 pack2(float lo, float hi) {
    u64 r; asm("mov.b64 %0, {%1,%2};" : "=l"(r) : "f"(lo), "f"(hi)); return r;
}
__device__ __forceinline__ float2 unpack2(u64 v) {
    float2 f; asm("mov.b64 {%0,%1}, %2;" : "=f"(f.x), "=f"(f.y) : "l"(v)); return f;
}

// ---------------------------------------------------------------------------
// Prep: transpose main-conv weights [O][C][3][3] -> [C][9][O]
// ---------------------------------------------------------------------------
__global__ void transpose_w_kernel(const float* __restrict__ w, float* __restrict__ wT)
{
    int idx = blockIdx.x * blockDim.x + threadIdx.x;
    if (idx >= Cc * Kk * Onc) return;
    int o = idx & (Onc - 1);
    int k = (idx >> 8) % Kk;
    int c = idx / (Kk * Onc);
    wT[idx] = w[((size_t)o * Cc + c) * Kk + k];
}

// Prep: transpose offset weights [27][C][3][3] -> [C][9][28] (padded)
__global__ void transpose_woff_kernel(const float* __restrict__ w, float* __restrict__ wT)
{
    int idx = blockIdx.x * blockDim.x + threadIdx.x;
    if (idx >= Cc * Kk * 28) return;
    int oc  = idx % 28;
    int tap = (idx / 28) % Kk;
    int c   = idx / (Kk * 28);
    wT[idx] = (oc < 27) ? w[((size_t)oc * Cc + c) * Kk + tap] : 0.f;
}

// ---------------------------------------------------------------------------
// Dynamic smem layout (bytes), total 56576, 2 CTAs/SM:
//   [0,      9216)  swgt  float4[576]
//   [9216,  18432)  sidx  int4[576]
//   [18432, 36864)  wsm   float[2*2304]   (phase-2 weights, 2 channels)
//   [36864, 46080)  ssm2  u64[2*576]      (pre-duplicated sample pairs)
// Phase-1 overlays:
//   [18432, 42240)  xs[16][120] + wo[16*252]
//   [42240, 56576)  om[2][64][28]
// ---------------------------------------------------------------------------
#define SWGT_O  0
#define SIDX_O  9216
#define WSM_O   18432
#define SSM_O   36864
#define XS_O    18432
#define WO_O    26112
#define OM_O    42240
#define SMEMSZ  56576

__global__ __launch_bounds__(256, 2) void dcn_fused_kernel(
    const float* __restrict__ x,
    const float* __restrict__ w_offT,  // [C][9][28]
    const float* __restrict__ b_off,   // [27]
    const float* __restrict__ wT,      // [C][9][O]
    const float* __restrict__ bias,    // [O]
    float* __restrict__ out)
{
    extern __shared__ __align__(16) char smem[];
    float4* swgt = (float4*)(smem + SWGT_O);
    int4*   sidx = (int4*)(smem + SIDX_O);

    int b   = blockIdx.y;
    int t   = blockIdx.x;             // 0..63
    int py0 = (t >> 3) * 8;
    int px0 = (t & 7) * 8;
    int tid = threadIdx.x;

    // ======================== Phase 1: offset conv ========================
    {
        float* xs_s = (float*)(smem + XS_O);           // [16][120]
        float* wo_s = (float*)(smem + WO_O);           // [16*252]
        float (*om_s)[64][28] = (float (*)[64][28])(smem + OM_O);

        int p   = tid & 63;
        int g   = tid >> 6;           // channel group 0..3
        int ppy = p >> 3;
        int ppx = p & 7;

        u64 aoff2[14];
#pragma unroll
        for (int j = 0; j < 14; j++) aoff2[j] = 0ull;

        for (int r = 0; r < 16; r++) {
            __syncthreads();
            // stage 16 channels' 10x10 halos (rows padded to 12)
            for (int i = tid; i < 1920; i += 256) {
                int ch  = i / 120;
                int rem = i - ch * 120;
                int rr  = rem / 12;
                int cc2 = rem - rr * 12;
                int c   = (r << 4) + ch;
                int gy  = py0 - 1 + rr;
                int gx  = px0 - 1 + cc2;
                float v = 0.f;
                if (cc2 < 10 && (unsigned)gy < (unsigned)Hh && (unsigned)gx < (unsigned)Ww)
                    v = __ldg(x + ((size_t)(b * Cc + c)) * HW + gy * Ww + gx);
                xs_s[ch * 120 + rem] = v;
            }
            // stage 16 channels' pre-transposed offset weights (coalesced)
            {
                const float4* wp4 = (const float4*)(w_offT + (size_t)(r << 4) * 252);
                float4* wo4 = (float4*)wo_s;
                for (int i = tid; i < 1008; i += 256) wo4[i] = __ldg(wp4 + i);
            }
            __syncthreads();

#pragma unroll
            for (int ci = 0; ci < 4; ci++) {
                int ch = (g << 2) + ci;
                const float* xrow = xs_s + ch * 120;
                float xv[9];
#pragma unroll
                for (int rr = 0; rr < 3; rr++)
#pragma unroll
                    for (int cc = 0; cc < 3; cc++)
                        xv[rr * 3 + cc] = xrow[(ppy + rr) * 12 + ppx + cc];

#pragma unroll
                for (int tap = 0; tap < 9; tap++) {
                    u64 xt2 = pack2(xv[tap], xv[tap]);
                    const ulonglong2* wr = (const ulonglong2*)(wo_s + ch * 252 + tap * 28);
#pragma unroll
                    for (int j = 0; j < 7; j++) {
                        ulonglong2 wv2 = wr[j];
                        FMA2(aoff2[2 * j],     xt2, wv2.x);
                        FMA2(aoff2[2 * j + 1], xt2, wv2.y);
                    }
                }
            }
        }
        __syncthreads();
        // two-step cross-group reduction into om[2][64][28]
        if (g >= 2) {
#pragma unroll
            for (int j = 0; j < 14; j++)
                *(u64*)&om_s[g - 2][p][2 * j] = aoff2[j];
        }
        __syncthreads();
        if (g < 2) {
#pragma unroll
            for (int j = 0; j < 14; j++) {
                u64 tacc = *(u64*)&om_s[g][p][2 * j];
                ADDP2(tacc, aoff2[j]);
                *(u64*)&om_s[g][p][2 * j] = tacc;
            }
        }
        __syncthreads();

        // ---- Coordinate / gather-weight precompute ----
        float (*omr)[64][28] = om_s;
        for (int i = tid; i < 576; i += 256) {
            int pp = i & 63;
            int k  = i >> 6;
            int gy = py0 + (pp >> 3);
            int gx = px0 + (pp & 7);
            float dy = __ldg(b_off + 2 * k)     + omr[0][pp][2 * k]     + omr[1][pp][2 * k];
            float dx = __ldg(b_off + 2 * k + 1) + omr[0][pp][2 * k + 1] + omr[1][pp][2 * k + 1];
            float mr = __ldg(b_off + 18 + k)    + omr[0][pp][18 + k]    + omr[1][pp][18 + k];
            float mv = 1.f / (1.f + expf(-mr));
            float ysv = (float)gy + (float)(k / 3 - 1) + dy;
            float xsv = (float)gx + (float)(k % 3 - 1) + dx;
            float y0f = floorf(ysv), x0f = floorf(xsv);
            float wy = ysv - y0f, wx = xsv - x0f;
            int y0 = (int)y0f, x0 = (int)x0f;
            int y1 = y0 + 1, x1 = x0 + 1;
            bool vy0 = (y0 >= 0) && (y0 < Hh);
            bool vy1 = (y1 >= 0) && (y1 < Hh);
            bool vx0 = (x0 >= 0) && (x0 < Ww);
            bool vx1 = (x1 >= 0) && (x1 < Ww);
            int y0c = min(max(y0, 0), Hh - 1), y1c = min(max(y1, 0), Hh - 1);
            int x0c = min(max(x0, 0), Ww - 1), x1c = min(max(x1, 0), Ww - 1);
            float4 wv;
            wv.x = (vy0 && vx0) ? mv * (1.f - wy) * (1.f - wx) : 0.f;
            wv.y = (vy0 && vx1) ? mv * (1.f - wy) * wx         : 0.f;
            wv.z = (vy1 && vx0) ? mv * wy * (1.f - wx)         : 0.f;
            wv.w = (vy1 && vx1) ? mv * wy * wx                 : 0.f;
            int4 iv;
            iv.x = y0c * Ww + x0c;
            iv.y = y0c * Ww + x1c;
            iv.z = y1c * Ww + x0c;
            iv.w = y1c * Ww + x1c;
            swgt[i] = wv;
            sidx[i] = iv;
        }
        __syncthreads();
    }

    // ================= Phase 2: sampling + GEMM + epilogue =================
    int to = tid >> 4;   // 0..15 -> o-base = to*16
    int tp = tid & 15;   // 0..15 -> p-base = tp*4

    u64 acc2[8][4];
#pragma unroll
    for (int i = 0; i < 8; i++)
#pragma unroll
        for (int j = 0; j < 4; j++) acc2[i][j] = 0ull;

    const float* xb = x + (size_t)b * Cc * HW;
    float* wsm = (float*)(smem + WSM_O);
    u64*   ssm2 = (u64*)(smem + SSM_O);

    for (int c0 = 0; c0 < Cc; c0 += 2) {
        const float* xp0 = xb + (size_t)c0 * HW;
        // stage sampled values for 2 channels as duplicated pairs
        for (int i = tid; i < 1152; i += 256) {
            int cc = (i >= 576);
            int r  = i - (cc ? 576 : 0);
            const float* xp = xp0 + cc * HW;
            float4 wv = swgt[r];
            int4   iv = sidx[r];
            float s = wv.x * __ldg(xp + iv.x) + wv.y * __ldg(xp + iv.y)
                    + wv.z * __ldg(xp + iv.z) + wv.w * __ldg(xp + iv.w);
            ssm2[i] = pack2(s, s);
        }
        // stage weights for 2 channels (coalesced float4 copy: 4608 floats)
        {
            const float4* wp4 = (const float4*)(wT + (size_t)c0 * 2304);
            float4* wsm4 = (float4*)wsm;
            for (int i = tid; i < 1152; i += 256) wsm4[i] = __ldg(wp4 + i);
        }
        __syncthreads();

#pragma unroll
        for (int cc = 0; cc < 2; cc++) {
            const float* wbase = wsm + cc * 2304 + (to << 4);
            const u64*   sbase = ssm2 + cc * 576 + (tp << 2);
#pragma unroll
            for (int k = 0; k < 9; k++) {
                const float* wr = wbase + k * 256;
                ulonglong2 w01 = *(const ulonglong2*)(wr);
                ulonglong2 w23 = *(const ulonglong2*)(wr + 4);
                ulonglong2 w45 = *(const ulonglong2*)(wr + 8);
                ulonglong2 w67 = *(const ulonglong2*)(wr + 12);
                ulonglong2 s01 = *(const ulonglong2*)(sbase + k * 64);
                ulonglong2 s23 = *(const ulonglong2*)(sbase + k * 64 + 2);
                u64 sp[4] = {s01.x, s01.y, s23.x, s23.y};
                u64 wp[8] = {w01.x, w01.y, w23.x, w23.y, w45.x, w45.y, w67.x, w67.y};
#pragma unroll
                for (int op = 0; op < 8; op++)
#pragma unroll
                    for (int jj = 0; jj < 4; jj++)
                        FMA2(acc2[op][jj], wp[op], sp[jj]);
            }
        }
        __syncthreads();
    }

    // epilogue: bias + ReLU, vectorized stores
    {
        int row = tp >> 1;
        int cb  = (tp & 1) << 2;
#pragma unroll
        for (int op = 0; op < 8; op++) {
            int o0 = (to << 4) + (op << 1);
            float bv0 = __ldg(bias + o0);
            float bv1 = __ldg(bias + o0 + 1);
            float2 v0 = unpack2(acc2[op][0]);
            float2 v1 = unpack2(acc2[op][1]);
            float2 v2 = unpack2(acc2[op][2]);
            float2 v3 = unpack2(acc2[op][3]);
            float4 lo, hi;
            lo.x = fmaxf(v0.x + bv0, 0.f); lo.y = fmaxf(v1.x + bv0, 0.f);
            lo.z = fmaxf(v2.x + bv0, 0.f); lo.w = fmaxf(v3.x + bv0, 0.f);
            hi.x = fmaxf(v0.y + bv1, 0.f); hi.y = fmaxf(v1.y + bv1, 0.f);
            hi.z = fmaxf(v2.y + bv1, 0.f); hi.w = fmaxf(v3.y + bv1, 0.f);
            size_t base0 = ((size_t)(b * Onc + o0) * Hh + py0 + row) * Ww + px0 + cb;
            size_t base1 = base0 + (size_t)Hh * Ww;
            *(float4*)(out + base0) = lo;
            *(float4*)(out + base1) = hi;
        }
    }
}

// ---------------------------------------------------------------------------
// Launch
// ---------------------------------------------------------------------------
extern "C" void kernel_launch(void* const* d_in, const int* in_sizes, int n_in,
                              void* d_out, int out_size)
{
    const float* x = (const float*)d_in[0];
    const float* w_off[3] = {(const float*)d_in[1], (const float*)d_in[5], (const float*)d_in[9]};
    const float* b_off[3] = {(const float*)d_in[2], (const float*)d_in[6], (const float*)d_in[10]};
    const float* wq[3]    = {(const float*)d_in[3], (const float*)d_in[7], (const float*)d_in[11]};
    const float* bias[3]  = {(const float*)d_in[4], (const float*)d_in[8], (const float*)d_in[12]};

    float *buf1, *buf2, *wT, *woT;
    cudaGetSymbolAddress((void**)&buf1, g_buf1);
    cudaGetSymbolAddress((void**)&buf2, g_buf2);
    cudaGetSymbolAddress((void**)&wT, g_wT);
    cudaGetSymbolAddress((void**)&woT, g_woT);

    cudaFuncSetAttribute(dcn_fused_kernel, cudaFuncAttributeMaxDynamicSharedMemorySize, SMEMSZ);

    for (int l = 0; l < 3; l++) {
        transpose_w_kernel<<<(Cc * Kk * Onc + 255) / 256, 256>>>(wq[l], wT + (size_t)l * Cc * Kk * Onc);
        transpose_woff_kernel<<<(Cc * Kk * 28 + 255) / 256, 256>>>(w_off[l], woT + (size_t)l * Cc * Kk * 28);
    }

    const float* src[3] = {x, buf1, buf2};
    float*       dst[3] = {buf1, buf2, (float*)d_out};

    for (int l = 0; l < 3; l++) {
        dcn_fused_kernel<<<dim3(64, Bn), 256, SMEMSZ>>>(src[l],
                                                        woT + (size_t)l * Cc * Kk * 28,
                                                        b_off[l],
                                                        wT + (size_t)l * Cc * Kk * Onc,
                                                        bias[l], dst[l]);
    }
}

// round 9
// speedup vs baseline: 1.4029x; 1.4029x over previous
#include <cuda_runtime.h>
#include <math.h>
#include <cstdint>

#define Bn 4
#define Cc 256
#define Onc 256
#define Hh 64
#define Ww 64
#define Kk 9
#define HW 4096

typedef unsigned long long u64;

// Scratch (static device arrays — no allocation)
__device__ float g_buf1[Bn * Cc * HW];
__device__ float g_buf2[Bn * Cc * HW];
__device__ float g_wT[3 * Cc * Kk * Onc];       // main weights [l][c][k][o]
__device__ float g_woT[3 * Cc * Kk * 28];       // offset weights [l][c][tap][28]

// ---- packed f32x2 helpers -------------------------------------------------
#define FMA2(d, a, b)  asm("fma.rn.f32x2 %0, %1, %2, %0;" : "+l"(d) : "l"(a), "l"(b))
#define ADDP2(d, a)    asm("add.rn.f32x2 %0, %1, %0;" : "+l"(d) : "l"(a))

__device__ __forceinline__ u64 pack2(float lo, float hi) {
    u64 r; asm("mov.b64 %0, {%1,%2};" : "=l"(r) : "f"(lo), "f"(hi)); return r;
}
__device__ __forceinline__ float2 unpack2(u64 v) {
    float2 f; asm("mov.b64 {%0,%1}, %2;" : "=f"(f.x), "=f"(f.y) : "l"(v)); return f;
}

// ---------------------------------------------------------------------------
// Prep: transpose main-conv weights [O][C][3][3] -> [C][9][O]
// ---------------------------------------------------------------------------
__global__ void transpose_w_kernel(const float* __restrict__ w, float* __restrict__ wT)
{
    int idx = blockIdx.x * blockDim.x + threadIdx.x;
    if (idx >= Cc * Kk * Onc) return;
    int o = idx & (Onc - 1);
    int k = (idx >> 8) % Kk;
    int c = idx / (Kk * Onc);
    wT[idx] = w[((size_t)o * Cc + c) * Kk + k];
}

// Prep: transpose offset weights [27][C][3][3] -> [C][9][28] (padded)
__global__ void transpose_woff_kernel(const float* __restrict__ w, float* __restrict__ wT)
{
    int idx = blockIdx.x * blockDim.x + threadIdx.x;
    if (idx >= Cc * Kk * 28) return;
    int oc  = idx % 28;
    int tap = (idx / 28) % Kk;
    int c   = idx / (Kk * 28);
    wT[idx] = (oc < 27) ? w[((size_t)oc * Cc + c) * Kk + tap] : 0.f;
}

// ---------------------------------------------------------------------------
// Fused kernel (R3 baseline + software-pipelined prefetch).
// Block 256 threads, tile 8x8 pixels x 256 outputs. Grid (64, B).
// ---------------------------------------------------------------------------
__global__ __launch_bounds__(256, 2) void dcn_fused_kernel(
    const float* __restrict__ x,
    const float* __restrict__ w_offT,  // [C][9][28]
    const float* __restrict__ b_off,   // [27]
    const float* __restrict__ wT,      // [C][9][O]
    const float* __restrict__ bias,    // [O]
    float* __restrict__ out)
{
    __shared__ __align__(16) union {
        struct {
            float xs[16][120];      // 16 channels x 10x12 halo
            float wo[16 * 252];     // 16 channels x 9 taps x 28
        } p1;
        struct {
            float4 swgt[576];       // premultiplied bilinear weights
            int4   sidx[576];       // clamped gather indices
        } p2;
    } u1;
    __shared__ __align__(16) union {
        float om[2][64][28];        // reduced offset-conv partials
        struct {
            float ssm[2 * 576];     // sampled values, 2 channels
            float wsm[2 * 2304];    // weights, 2 channels
        } p2;
    } u2;

    int b   = blockIdx.y;
    int t   = blockIdx.x;             // 0..63
    int py0 = (t >> 3) * 8;
    int px0 = (t & 7) * 8;
    int tid = threadIdx.x;

    // ======================== Phase 1: offset conv ========================
    {
        int p   = tid & 63;
        int g   = tid >> 6;           // channel group 0..3
        int ppy = p >> 3;
        int ppx = p & 7;

        u64 aoff2[14];
#pragma unroll
        for (int j = 0; j < 14; j++) aoff2[j] = 0ull;

        // pipelined staging registers for the next round
        float  hpf[8];
        float4 wpf[4];

        // prefetch round 0
        {
            const float4* wp4 = (const float4*)w_offT;
#pragma unroll
            for (int i8 = 0; i8 < 8; i8++) {
                int i = tid + 256 * i8;
                float v = 0.f;
                if (i < 1920) {
                    int ch  = i / 120;
                    int rem = i - ch * 120;
                    int rr  = rem / 12;
                    int cc2 = rem - rr * 12;
                    int gy  = py0 - 1 + rr;
                    int gx  = px0 - 1 + cc2;
                    if (cc2 < 10 && (unsigned)gy < (unsigned)Hh && (unsigned)gx < (unsigned)Ww)
                        v = __ldg(x + ((size_t)(b * Cc + ch)) * HW + gy * Ww + gx);
                }
                hpf[i8] = v;
            }
#pragma unroll
            for (int i4 = 0; i4 < 4; i4++) {
                int i = tid + 256 * i4;
                if (i < 1008) wpf[i4] = __ldg(wp4 + i);
            }
        }

        for (int r = 0; r < 16; r++) {
            __syncthreads();          // previous round's compute done reading xs/wo
            // commit prefetched halo + weights to smem
#pragma unroll
            for (int i8 = 0; i8 < 8; i8++) {
                int i = tid + 256 * i8;
                if (i < 1920) {
                    int ch  = i / 120;
                    int rem = i - ch * 120;
                    u1.p1.xs[ch][rem] = hpf[i8];
                }
            }
            {
                float4* wo4 = (float4*)u1.p1.wo;
#pragma unroll
                for (int i4 = 0; i4 < 4; i4++) {
                    int i = tid + 256 * i4;
                    if (i < 1008) wo4[i] = wpf[i4];
                }
            }
            __syncthreads();

            // issue prefetch for round r+1 (overlaps with compute below)
            if (r < 15) {
                int rn = r + 1;
                const float4* wp4 = (const float4*)(w_offT + (size_t)(rn << 4) * 252);
#pragma unroll
                for (int i8 = 0; i8 < 8; i8++) {
                    int i = tid + 256 * i8;
                    float v = 0.f;
                    if (i < 1920) {
                        int ch  = i / 120;
                        int rem = i - ch * 120;
                        int rr  = rem / 12;
                        int cc2 = rem - rr * 12;
                        int c   = (rn << 4) + ch;
                        int gy  = py0 - 1 + rr;
                        int gx  = px0 - 1 + cc2;
                        if (cc2 < 10 && (unsigned)gy < (unsigned)Hh && (unsigned)gx < (unsigned)Ww)
                            v = __ldg(x + ((size_t)(b * Cc + c)) * HW + gy * Ww + gx);
                    }
                    hpf[i8] = v;
                }
#pragma unroll
                for (int i4 = 0; i4 < 4; i4++) {
                    int i = tid + 256 * i4;
                    if (i < 1008) wpf[i4] = __ldg(wp4 + i);
                }
            }

#pragma unroll
            for (int ci = 0; ci < 4; ci++) {
                int ch = (g << 2) + ci;
                const float* xrow = u1.p1.xs[ch];
                float xv[9];
#pragma unroll
                for (int rr = 0; rr < 3; rr++)
#pragma unroll
                    for (int cc = 0; cc < 3; cc++)
                        xv[rr * 3 + cc] = xrow[(ppy + rr) * 12 + ppx + cc];

#pragma unroll
                for (int tap = 0; tap < 9; tap++) {
                    u64 xt2 = pack2(xv[tap], xv[tap]);
                    const ulonglong2* wr = (const ulonglong2*)(u1.p1.wo + ch * 252 + tap * 28);
#pragma unroll
                    for (int j = 0; j < 7; j++) {
                        ulonglong2 wv2 = wr[j];
                        FMA2(aoff2[2 * j],     xt2, wv2.x);
                        FMA2(aoff2[2 * j + 1], xt2, wv2.y);
                    }
                }
            }
        }
        __syncthreads();
        // two-step cross-group reduction into u2.om[2][64][28]
        if (g >= 2) {
#pragma unroll
            for (int j = 0; j < 14; j++)
                *(u64*)&u2.om[g - 2][p][2 * j] = aoff2[j];
        }
        __syncthreads();
        if (g < 2) {
#pragma unroll
            for (int j = 0; j < 14; j++) {
                u64 tacc = *(u64*)&u2.om[g][p][2 * j];
                ADDP2(tacc, aoff2[j]);
                *(u64*)&u2.om[g][p][2 * j] = tacc;
            }
        }
        __syncthreads();
    }

    // ============= Coordinate / gather-weight precompute =============
    {
        float4 rw[3];
        int4   ri[3];
#pragma unroll
        for (int j = 0; j < 3; j++) {
            int i = tid + j * 256;
            if (i < 576) {
                int p = i & 63;
                int k = i >> 6;
                int gy = py0 + (p >> 3);
                int gx = px0 + (p & 7);
                float dy = __ldg(b_off + 2 * k)     + u2.om[0][p][2 * k]     + u2.om[1][p][2 * k];
                float dx = __ldg(b_off + 2 * k + 1) + u2.om[0][p][2 * k + 1] + u2.om[1][p][2 * k + 1];
                float mr = __ldg(b_off + 18 + k)    + u2.om[0][p][18 + k]    + u2.om[1][p][18 + k];
                float mv = 1.f / (1.f + expf(-mr));
                float ysv = (float)gy + (float)(k / 3 - 1) + dy;
                float xsv = (float)gx + (float)(k % 3 - 1) + dx;
                float y0f = floorf(ysv), x0f = floorf(xsv);
                float wy = ysv - y0f, wx = xsv - x0f;
                int y0 = (int)y0f, x0 = (int)x0f;
                int y1 = y0 + 1, x1 = x0 + 1;
                bool vy0 = (y0 >= 0) && (y0 < Hh);
                bool vy1 = (y1 >= 0) && (y1 < Hh);
                bool vx0 = (x0 >= 0) && (x0 < Ww);
                bool vx1 = (x1 >= 0) && (x1 < Ww);
                int y0c = min(max(y0, 0), Hh - 1), y1c = min(max(y1, 0), Hh - 1);
                int x0c = min(max(x0, 0), Ww - 1), x1c = min(max(x1, 0), Ww - 1);
                float4 wv;
                wv.x = (vy0 && vx0) ? mv * (1.f - wy) * (1.f - wx) : 0.f;
                wv.y = (vy0 && vx1) ? mv * (1.f - wy) * wx         : 0.f;
                wv.z = (vy1 && vx0) ? mv * wy * (1.f - wx)         : 0.f;
                wv.w = (vy1 && vx1) ? mv * wy * wx                 : 0.f;
                rw[j] = wv;
                int4 iv;
                iv.x = y0c * Ww + x0c;
                iv.y = y0c * Ww + x1c;
                iv.z = y1c * Ww + x0c;
                iv.w = y1c * Ww + x1c;
                ri[j] = iv;
            }
        }
        __syncthreads();   // all om reads done before overwriting union with p2
#pragma unroll
        for (int j = 0; j < 3; j++) {
            int i = tid + j * 256;
            if (i < 576) {
                u1.p2.swgt[i] = rw[j];
                u1.p2.sidx[i] = ri[j];
            }
        }
        __syncthreads();
    }

    // ================= Phase 2: sampling + GEMM + epilogue =================
    int to = tid >> 4;   // 0..15 -> o-base = to*16
    int tp = tid & 15;   // 0..15 -> p-base = tp*4

    u64 acc2[8][4];
#pragma unroll
    for (int i = 0; i < 8; i++)
#pragma unroll
        for (int j = 0; j < 4; j++) acc2[i][j] = 0ull;

    const float* xb = x + (size_t)b * Cc * HW;

    // sample prefetch registers: 5 entries x 4 taps (entry 4 only for tid<128)
    float pf[5][4];

    // prefetch chunk 0
    {
#pragma unroll
        for (int q = 0; q < 5; q++) {
            int i = tid + 256 * q;
            if (q < 4 || tid < 128) {
                int cc = (i >= 576);
                int r  = i - (cc ? 576 : 0);
                int4 iv = u1.p2.sidx[r];
                const float* xp = xb + (size_t)cc * HW;
                pf[q][0] = __ldg(xp + iv.x);
                pf[q][1] = __ldg(xp + iv.y);
                pf[q][2] = __ldg(xp + iv.z);
                pf[q][3] = __ldg(xp + iv.w);
            }
        }
    }

    for (int c0 = 0; c0 < Cc; c0 += 2) {
        // commit prefetched samples (combine + STS) for this chunk
#pragma unroll
        for (int q = 0; q < 5; q++) {
            int i = tid + 256 * q;
            if (q < 4 || tid < 128) {
                int cc = (i >= 576);
                int r  = i - (cc ? 576 : 0);
                float4 wv = u1.p2.swgt[r];
                u2.p2.ssm[i] = wv.x * pf[q][0] + wv.y * pf[q][1]
                             + wv.z * pf[q][2] + wv.w * pf[q][3];
            }
        }
        // stage weights for 2 channels (coalesced float4 copy: 4608 floats)
        {
            const float4* wp4 = (const float4*)(wT + (size_t)c0 * 2304);
            float4* wsm4 = (float4*)u2.p2.wsm;
#pragma unroll
            for (int q = 0; q < 5; q++) {
                int i = tid + 256 * q;
                if (q < 4 || tid < 128) wsm4[i] = __ldg(wp4 + i);
            }
        }
        __syncthreads();

        // issue sample prefetch for the next chunk (overlaps with GEMM below)
        if (c0 + 2 < Cc) {
            const float* xn = xb + (size_t)(c0 + 2) * HW;
#pragma unroll
            for (int q = 0; q < 5; q++) {
                int i = tid + 256 * q;
                if (q < 4 || tid < 128) {
                    int cc = (i >= 576);
                    int r  = i - (cc ? 576 : 0);
                    int4 iv = u1.p2.sidx[r];
                    const float* xp = xn + (size_t)cc * HW;
                    pf[q][0] = __ldg(xp + iv.x);
                    pf[q][1] = __ldg(xp + iv.y);
                    pf[q][2] = __ldg(xp + iv.z);
                    pf[q][3] = __ldg(xp + iv.w);
                }
            }
        }

#pragma unroll
        for (int cc = 0; cc < 2; cc++) {
#pragma unroll
            for (int k = 0; k < 9; k++) {
                const float* wr = u2.p2.wsm + cc * 2304 + k * 256 + (to << 4);
                ulonglong2 w01 = *(const ulonglong2*)(wr);
                ulonglong2 w23 = *(const ulonglong2*)(wr + 4);
                ulonglong2 w45 = *(const ulonglong2*)(wr + 8);
                ulonglong2 w67 = *(const ulonglong2*)(wr + 12);
                float4 sv = *(const float4*)(u2.p2.ssm + cc * 576 + k * 64 + (tp << 2));
                u64 sp[4];
                sp[0] = pack2(sv.x, sv.x);
                sp[1] = pack2(sv.y, sv.y);
                sp[2] = pack2(sv.z, sv.z);
                sp[3] = pack2(sv.w, sv.w);
                u64 wp[8] = {w01.x, w01.y, w23.x, w23.y, w45.x, w45.y, w67.x, w67.y};
#pragma unroll
                for (int op = 0; op < 8; op++)
#pragma unroll
                    for (int jj = 0; jj < 4; jj++)
                        FMA2(acc2[op][jj], wp[op], sp[jj]);
            }
        }
        __syncthreads();
    }

    // epilogue: bias + ReLU, vectorized stores
    {
        int row = tp >> 1;
        int cb  = (tp & 1) << 2;
#pragma unroll
        for (int op = 0; op < 8; op++) {
            int o0 = (to << 4) + (op << 1);
            float bv0 = __ldg(bias + o0);
            float bv1 = __ldg(bias + o0 + 1);
            float2 v0 = unpack2(acc2[op][0]);
            float2 v1 = unpack2(acc2[op][1]);
            float2 v2 = unpack2(acc2[op][2]);
            float2 v3 = unpack2(acc2[op][3]);
            float4 lo, hi;
            lo.x = fmaxf(v0.x + bv0, 0.f); lo.y = fmaxf(v1.x + bv0, 0.f);
            lo.z = fmaxf(v2.x + bv0, 0.f); lo.w = fmaxf(v3.x + bv0, 0.f);
            hi.x = fmaxf(v0.y + bv1, 0.f); hi.y = fmaxf(v1.y + bv1, 0.f);
            hi.z = fmaxf(v2.y + bv1, 0.f); hi.w = fmaxf(v3.y + bv1, 0.f);
            size_t base0 = ((size_t)(b * Onc + o0) * Hh + py0 + row) * Ww + px0 + cb;
            size_t base1 = base0 + (size_t)Hh * Ww;
            *(float4*)(out + base0) = lo;
            *(float4*)(out + base1) = hi;
        }
    }
}

// ---------------------------------------------------------------------------
// Launch
// ---------------------------------------------------------------------------
extern "C" void kernel_launch(void* const* d_in, const int* in_sizes, int n_in,
                              void* d_out, int out_size)
{
    const float* x = (const float*)d_in[0];
    const float* w_off[3] = {(const float*)d_in[1], (const float*)d_in[5], (const float*)d_in[9]};
    const float* b_off[3] = {(const float*)d_in[2], (const float*)d_in[6], (const float*)d_in[10]};
    const float* wq[3]    = {(const float*)d_in[3], (const float*)d_in[7], (const float*)d_in[11]};
    const float* bias[3]  = {(const float*)d_in[4], (const float*)d_in[8], (const float*)d_in[12]};

    float *buf1, *buf2, *wT, *woT;
    cudaGetSymbolAddress((void**)&buf1, g_buf1);
    cudaGetSymbolAddress((void**)&buf2, g_buf2);
    cudaGetSymbolAddress((void**)&wT, g_wT);
    cudaGetSymbolAddress((void**)&woT, g_woT);

    for (int l = 0; l < 3; l++) {
        transpose_w_kernel<<<(Cc * Kk * Onc + 255) / 256, 256>>>(wq[l], wT + (size_t)l * Cc * Kk * Onc);
        transpose_woff_kernel<<<(Cc * Kk * 28 + 255) / 256, 256>>>(w_off[l], woT + (size_t)l * Cc * Kk * 28);
    }

    const float* src[3] = {x, buf1, buf2};
    float*       dst[3] = {buf1, buf2, (float*)d_out};

    for (int l = 0; l < 3; l++) {
        dcn_fused_kernel<<<dim3(64, Bn), 256>>>(src[l],
                                                woT + (size_t)l * Cc * Kk * 28,
                                                b_off[l],
                                                wT + (size_t)l * Cc * Kk * Onc,
                                                bias[l], dst[l]);
    }
}